// round 3
// baseline (speedup 1.0000x reference)
#include <cuda_runtime.h>
#include <math.h>

#define NUM_J 23
#define P_POSES 16
#define BLK 256
#define VPB (2*BLK)   // 512 vertices per block (2 adjacent per thread)

typedef unsigned long long ull;

// Pose-pair interleaved A matrices: [pp(8)][j(23)][m(12)][pose_parity(2)] floats
__device__ float g_A[8 * NUM_J * 24];

__device__ __forceinline__ ull fma2(ull a, ull b, ull c) {
    ull d;
    asm("fma.rn.f32x2 %0, %1, %2, %3;" : "=l"(d) : "l"(a), "l"(b), "l"(c));
    return d;
}
__device__ __forceinline__ ull packf2(float lo, float hi) {
    ull r;
    asm("mov.b64 %0, {%1, %2};" : "=l"(r) : "f"(lo), "f"(hi));
    return r;
}
__device__ __forceinline__ void unpackf2(ull v, float& lo, float& hi) {
    asm("mov.b64 {%0, %1}, %2;" : "=f"(lo), "=f"(hi) : "l"(v));
}

// ---------------------------------------------------------------------------
// Kernel 1: setup, parallelized. 1 block, 384 threads.
//  phase1: thread (p,j) computes Rodrigues R + rel translation  (parallel)
//  phase2: thread p composes the 23-joint kinematic chain        (serial/pose)
//  phase3: thread (p,j) emits A (shift folded) + joints output   (parallel)
// ---------------------------------------------------------------------------
struct SetupArgs {
    const float* joints;    // (23,3)
    const float* disp;      // (16,1,3)
    const float* rnd;       // (16,3)
    const float* prm[11];   // each (16,3)
    float* outJ;            // -> d_out + 16*V*3
};

__device__ const int   c_parents[NUM_J] = {-1,0,1,1,3,4,5,4,7,4,9,1,11,12,13,12,15,12,17,0,19,0,21};
__device__ const int   c_slot[NUM_J]    = { 0,-1,-1,1,2,3,-1,4,-1,5,-1,6,7,8,-1,9,-1,10,-1,-1,-1,-1,-1};
__device__ const float c_scale[11]      = {0.7853981633974483f, 1.5707963267948966f, 1.5707963267948966f,
                                           0.7853981633974483f, 0.7853981633974483f, 0.7853981633974483f,
                                           1.5707963267948966f, 1.5707963267948966f, 0.7853981633974483f,
                                           0.7853981633974483f, 0.7853981633974483f};

__global__ void lbs_setup(SetupArgs a) {
    __shared__ float sR[P_POSES][NUM_J][12];   // R(9) + rel(3)
    __shared__ float sG[P_POSES][NUM_J][12];   // chained G: R(9) + t(3)
    __shared__ float sSh[P_POSES][3];

    int t = threadIdx.x;
    int p = t / NUM_J;
    int j = t - p * NUM_J;

    // ---- phase 1: per-(p,j) rotation + rel; per-p shift ----
    if (t < P_POSES) {
        sSh[t][0] = a.rnd[t*3+0] + 3.0f * tanhf(a.disp[t*3+0]);
        sSh[t][1] = a.rnd[t*3+1] + 3.0f * tanhf(a.disp[t*3+1]);
        sSh[t][2] = a.rnd[t*3+2] + 3.0f * tanhf(a.disp[t*3+2]);
    }
    if (t < P_POSES * NUM_J) {
        float* R = sR[p][j];
        int s = c_slot[j];
        if (s < 0) {
            R[0]=1.f;R[1]=0.f;R[2]=0.f; R[3]=0.f;R[4]=1.f;R[5]=0.f; R[6]=0.f;R[7]=0.f;R[8]=1.f;
        } else {
            float sc = c_scale[s];
            float r0 = sc * tanhf(a.prm[s][p*3+0]);
            float r1 = sc * tanhf(a.prm[s][p*3+1]);
            float r2 = sc * tanhf(a.prm[s][p*3+2]);
            float ang = sqrtf(r0*r0 + r1*r1 + r2*r2 + 1e-16f);
            float inv = 1.0f / ang;
            float ax = r0*inv, ay = r1*inv, az = r2*inv;
            float sn = sinf(ang), cs = cosf(ang), omc = 1.0f - cs;
            R[0] = cs + omc*ax*ax;      R[1] = omc*ax*ay - sn*az;  R[2] = omc*ax*az + sn*ay;
            R[3] = omc*ax*ay + sn*az;   R[4] = cs + omc*ay*ay;     R[5] = omc*ay*az - sn*ax;
            R[6] = omc*ax*az - sn*ay;   R[7] = omc*ay*az + sn*ax;  R[8] = cs + omc*az*az;
        }
        int par = c_parents[j];
        float rel0 = a.joints[j*3+0], rel1 = a.joints[j*3+1], rel2 = a.joints[j*3+2];
        if (par >= 0) { rel0 -= a.joints[par*3+0]; rel1 -= a.joints[par*3+1]; rel2 -= a.joints[par*3+2]; }
        R[9] = rel0; R[10] = rel1; R[11] = rel2;
    }
    __syncthreads();

    // ---- phase 2: serial kinematic chain per pose ----
    if (t < P_POSES) {
        int pp = t;
        for (int jj = 0; jj < NUM_J; jj++) {
            const float* R = sR[pp][jj];
            float* G = sG[pp][jj];
            if (jj == 0) {
                for (int m = 0; m < 12; m++) G[m] = R[m];
            } else {
                const float* Gp = sG[pp][c_parents[jj]];
                for (int r = 0; r < 3; r++)
                    for (int c = 0; c < 3; c++)
                        G[r*3+c] = Gp[r*3+0]*R[0*3+c] + Gp[r*3+1]*R[1*3+c] + Gp[r*3+2]*R[2*3+c];
                for (int r = 0; r < 3; r++)
                    G[9+r] = Gp[r*3+0]*R[9] + Gp[r*3+1]*R[10] + Gp[r*3+2]*R[11] + Gp[9+r];
            }
        }
    }
    __syncthreads();

    // ---- phase 3: emit A + joints out, parallel over (p,j) ----
    if (t < P_POSES * NUM_J) {
        const float* G = sG[p][j];
        float sh0 = sSh[p][0], sh1 = sSh[p][1], sh2 = sSh[p][2];

        a.outJ[(p*NUM_J + j)*3 + 0] = G[9]  + sh0;
        a.outJ[(p*NUM_J + j)*3 + 1] = G[10] + sh1;
        a.outJ[(p*NUM_J + j)*3 + 2] = G[11] + sh2;

        float jr0 = a.joints[j*3+0], jr1 = a.joints[j*3+1], jr2 = a.joints[j*3+2];
        float tt[3];
        tt[0] = G[9]  - (G[0]*jr0 + G[1]*jr1 + G[2]*jr2) + sh0;
        tt[1] = G[10] - (G[3]*jr0 + G[4]*jr1 + G[5]*jr2) + sh1;
        tt[2] = G[11] - (G[6]*jr0 + G[7]*jr1 + G[8]*jr2) + sh2;

        int baseA = ((p >> 1) * NUM_J + j) * 24 + (p & 1);
        for (int i = 0; i < 3; i++) {
            for (int k = 0; k < 3; k++)
                g_A[baseA + (i*4 + k) * 2] = G[i*3 + k];
            g_A[baseA + (i*4 + 3) * 2] = tt[i];
        }
    }
}

// ---------------------------------------------------------------------------
// Kernel 2: 2 adjacent vertices per thread, 2 pose-pairs (4 poses) per inner
// pass. Per joint: 48 fma2 against 12 broadcast LDS.128 + 1 LDS.64.
// ---------------------------------------------------------------------------
__global__ __launch_bounds__(BLK, 3) void lbs_main(const float* __restrict__ verts,
                                                   const float* __restrict__ weights,
                                                   float* __restrict__ out, int V) {
    extern __shared__ float smem[];
    float*  sA  = smem;                              // 8*23*24 floats = 17664 B
    float2* sW2 = (float2*)(smem + 8*NUM_J*24);      // [j][pair] 23*256 float2 = 47104 B

    int tid  = threadIdx.x;
    int base = blockIdx.x * VPB;
    int nvb  = min(VPB, V - base);

    for (int i = tid; i < 8*NUM_J*24; i += BLK) sA[i] = g_A[i];
    float* sWf = (float*)sW2;
    for (int i = tid; i < nvb*NUM_J; i += BLK) {
        int vloc = i / NUM_J;
        int j    = i - vloc*NUM_J;
        sWf[(j*BLK + (vloc>>1))*2 + (vloc&1)] = weights[(size_t)base*NUM_J + i];
    }
    __syncthreads();

    if (2*tid >= nvb) return;
    int  v0 = base + 2*tid;
    bool bv = (2*tid + 1) < nvb;

    float xa, ya, za, xb, yb, zb;
    if (bv) {
        const float2* vv = (const float2*)verts;
        size_t h = (size_t)v0 * 3 / 2;   // v0 even
        float2 f0 = vv[h], f1 = vv[h+1], f2 = vv[h+2];
        xa = f0.x; ya = f0.y; za = f1.x;
        xb = f1.y; yb = f2.x; zb = f2.y;
    } else {
        xa = verts[(size_t)v0*3+0]; ya = verts[(size_t)v0*3+1]; za = verts[(size_t)v0*3+2];
        xb = 0.f; yb = 0.f; zb = 0.f;
    }
    ull xa2 = packf2(xa,xa), ya2 = packf2(ya,ya), za2 = packf2(za,za);
    ull xb2 = packf2(xb,xb), yb2 = packf2(yb,yb), zb2 = packf2(zb,zb);

    size_t V3   = (size_t)V * 3;
    float* outv = out + (size_t)v0 * 3;

#pragma unroll 1
    for (int pp2 = 0; pp2 < 4; pp2++) {
        const ulonglong2* aA = ((const ulonglong2*)sA) + (2*pp2)   * (NUM_J * 6);
        const ulonglong2* aB = ((const ulonglong2*)sA) + (2*pp2+1) * (NUM_J * 6);

        // pose-pair A (poses 4*pp2+0/1): vertex a -> acA*, vertex b -> acB*
        // pose-pair B (poses 4*pp2+2/3): vertex a -> acC*, vertex b -> acD*
        ull acA0=0, acA1=0, acA2=0, acB0=0, acB1=0, acB2=0;
        ull acC0=0, acC1=0, acC2=0, acD0=0, acD1=0, acD2=0;

#pragma unroll
        for (int j = 0; j < NUM_J; j++) {
            float2 wab = sW2[j*BLK + tid];
            ull wa = packf2(wab.x, wab.x);
            ull wb = packf2(wab.y, wab.y);

            {
                ulonglong2 q0 = aA[j*6+0], q1 = aA[j*6+1], q2 = aA[j*6+2];
                ulonglong2 q3 = aA[j*6+3], q4 = aA[j*6+4], q5 = aA[j*6+5];
                ull u;
                u = fma2(xa2, q0.x, fma2(ya2, q0.y, fma2(za2, q1.x, q1.y)));
                acA0 = fma2(wa, u, acA0);
                u = fma2(xa2, q2.x, fma2(ya2, q2.y, fma2(za2, q3.x, q3.y)));
                acA1 = fma2(wa, u, acA1);
                u = fma2(xa2, q4.x, fma2(ya2, q4.y, fma2(za2, q5.x, q5.y)));
                acA2 = fma2(wa, u, acA2);
                u = fma2(xb2, q0.x, fma2(yb2, q0.y, fma2(zb2, q1.x, q1.y)));
                acB0 = fma2(wb, u, acB0);
                u = fma2(xb2, q2.x, fma2(yb2, q2.y, fma2(zb2, q3.x, q3.y)));
                acB1 = fma2(wb, u, acB1);
                u = fma2(xb2, q4.x, fma2(yb2, q4.y, fma2(zb2, q5.x, q5.y)));
                acB2 = fma2(wb, u, acB2);
            }
            {
                ulonglong2 q0 = aB[j*6+0], q1 = aB[j*6+1], q2 = aB[j*6+2];
                ulonglong2 q3 = aB[j*6+3], q4 = aB[j*6+4], q5 = aB[j*6+5];
                ull u;
                u = fma2(xa2, q0.x, fma2(ya2, q0.y, fma2(za2, q1.x, q1.y)));
                acC0 = fma2(wa, u, acC0);
                u = fma2(xa2, q2.x, fma2(ya2, q2.y, fma2(za2, q3.x, q3.y)));
                acC1 = fma2(wa, u, acC1);
                u = fma2(xa2, q4.x, fma2(ya2, q4.y, fma2(za2, q5.x, q5.y)));
                acC2 = fma2(wa, u, acC2);
                u = fma2(xb2, q0.x, fma2(yb2, q0.y, fma2(zb2, q1.x, q1.y)));
                acD0 = fma2(wb, u, acD0);
                u = fma2(xb2, q2.x, fma2(yb2, q2.y, fma2(zb2, q3.x, q3.y)));
                acD1 = fma2(wb, u, acD1);
                u = fma2(xb2, q4.x, fma2(yb2, q4.y, fma2(zb2, q5.x, q5.y)));
                acD2 = fma2(wb, u, acD2);
            }
        }

        float a0l,a0h,a1l,a1h,a2l,a2h, b0l,b0h,b1l,b1h,b2l,b2h;
        float c0l,c0h,c1l,c1h,c2l,c2h, d0l,d0h,d1l,d1h,d2l,d2h;
        unpackf2(acA0,a0l,a0h); unpackf2(acA1,a1l,a1h); unpackf2(acA2,a2l,a2h);
        unpackf2(acB0,b0l,b0h); unpackf2(acB1,b1l,b1h); unpackf2(acB2,b2l,b2h);
        unpackf2(acC0,c0l,c0h); unpackf2(acC1,c1l,c1h); unpackf2(acC2,c2l,c2h);
        unpackf2(acD0,d0l,d0h); unpackf2(acD1,d1l,d1h); unpackf2(acD2,d2l,d2h);

        float* o0 = outv + (size_t)(4*pp2)   * V3;  // pose 4pp2+0
        float* o1 = o0 + V3;                         // pose 4pp2+1
        float* o2 = outv + (size_t)(4*pp2+2) * V3;  // pose 4pp2+2
        float* o3 = o2 + V3;                         // pose 4pp2+3
        if (bv) {
            ((float2*)o0)[0] = make_float2(a0l, a1l);
            ((float2*)o0)[1] = make_float2(a2l, b0l);
            ((float2*)o0)[2] = make_float2(b1l, b2l);
            ((float2*)o1)[0] = make_float2(a0h, a1h);
            ((float2*)o1)[1] = make_float2(a2h, b0h);
            ((float2*)o1)[2] = make_float2(b1h, b2h);
            ((float2*)o2)[0] = make_float2(c0l, c1l);
            ((float2*)o2)[1] = make_float2(c2l, d0l);
            ((float2*)o2)[2] = make_float2(d1l, d2l);
            ((float2*)o3)[0] = make_float2(c0h, c1h);
            ((float2*)o3)[1] = make_float2(c2h, d0h);
            ((float2*)o3)[2] = make_float2(d1h, d2h);
        } else {
            o0[0] = a0l; o0[1] = a1l; o0[2] = a2l;
            o1[0] = a0h; o1[1] = a1h; o1[2] = a2h;
            o2[0] = c0l; o2[1] = c1l; o2[2] = c2l;
            o3[0] = c0h; o3[1] = c1h; o3[2] = c2h;
        }
    }
}

// ---------------------------------------------------------------------------
extern "C" void kernel_launch(void* const* d_in, const int* in_sizes, int n_in,
                              void* d_out, int out_size) {
    const float* vertices = (const float*)d_in[0];   // (1,V,3)
    const float* joints   = (const float*)d_in[1];   // (1,23,3)
    const float* weights  = (const float*)d_in[2];   // (V,23)
    const float* disp     = (const float*)d_in[3];   // (16,1,3)
    const float* rnd      = (const float*)d_in[4];   // (16,3)

    int V = in_sizes[0] / 3;
    float* out = (float*)d_out;

    SetupArgs sa;
    sa.joints = joints;
    sa.disp   = disp;
    sa.rnd    = rnd;
    for (int i = 0; i < 11; i++) sa.prm[i] = (const float*)d_in[5 + i];
    sa.outJ = out + (size_t)P_POSES * V * 3;

    size_t shmem = (size_t)(8*NUM_J*24)*4 + (size_t)NUM_J*BLK*8;  // 64768 B
    cudaFuncSetAttribute(lbs_main, cudaFuncAttributeMaxDynamicSharedMemorySize, (int)shmem);

    lbs_setup<<<1, 384>>>(sa);

    int blocks = (V + VPB - 1) / VPB;
    lbs_main<<<blocks, BLK, shmem>>>(vertices, weights, out, V);
}

// round 4
// speedup vs baseline: 1.0493x; 1.0493x over previous
#include <cuda_runtime.h>
#include <math.h>

#define NUM_J 23
#define P_POSES 16
#define BLK 128
#define VT 4
#define VPB (VT*BLK)   // 512 vertices per block

typedef unsigned long long ull;

// Pose-pair interleaved A matrices: [pp(8)][j(23)][m(12)][pose_parity(2)] floats
__device__ __align__(16) float g_A[8 * NUM_J * 24];

__device__ __forceinline__ ull fma2(ull a, ull b, ull c) {
    ull d;
    asm("fma.rn.f32x2 %0, %1, %2, %3;" : "=l"(d) : "l"(a), "l"(b), "l"(c));
    return d;
}
__device__ __forceinline__ ull packf2(float lo, float hi) {
    ull r;
    asm("mov.b64 %0, {%1, %2};" : "=l"(r) : "f"(lo), "f"(hi));
    return r;
}
__device__ __forceinline__ void unpackf2(ull v, float& lo, float& hi) {
    asm("mov.b64 {%0, %1}, %2;" : "=f"(lo), "=f"(hi) : "l"(v));
}

// ---------------------------------------------------------------------------
// Kernel 1: setup (parallelized, 1 block x 384 threads).
// ---------------------------------------------------------------------------
struct SetupArgs {
    const float* joints;    // (23,3)
    const float* disp;      // (16,1,3)
    const float* rnd;       // (16,3)
    const float* prm[11];   // each (16,3)
    float* outJ;            // -> d_out + 16*V*3
};

__device__ const int   c_parents[NUM_J] = {-1,0,1,1,3,4,5,4,7,4,9,1,11,12,13,12,15,12,17,0,19,0,21};
__device__ const int   c_slot[NUM_J]    = { 0,-1,-1,1,2,3,-1,4,-1,5,-1,6,7,8,-1,9,-1,10,-1,-1,-1,-1,-1};
__device__ const float c_scale[11]      = {0.7853981633974483f, 1.5707963267948966f, 1.5707963267948966f,
                                           0.7853981633974483f, 0.7853981633974483f, 0.7853981633974483f,
                                           1.5707963267948966f, 1.5707963267948966f, 0.7853981633974483f,
                                           0.7853981633974483f, 0.7853981633974483f};

__global__ void lbs_setup(SetupArgs a) {
    __shared__ float sR[P_POSES][NUM_J][12];
    __shared__ float sG[P_POSES][NUM_J][12];
    __shared__ float sSh[P_POSES][3];

    int t = threadIdx.x;
    int p = t / NUM_J;
    int j = t - p * NUM_J;

    if (t < P_POSES) {
        sSh[t][0] = a.rnd[t*3+0] + 3.0f * tanhf(a.disp[t*3+0]);
        sSh[t][1] = a.rnd[t*3+1] + 3.0f * tanhf(a.disp[t*3+1]);
        sSh[t][2] = a.rnd[t*3+2] + 3.0f * tanhf(a.disp[t*3+2]);
    }
    if (t < P_POSES * NUM_J) {
        float* R = sR[p][j];
        int s = c_slot[j];
        if (s < 0) {
            R[0]=1.f;R[1]=0.f;R[2]=0.f; R[3]=0.f;R[4]=1.f;R[5]=0.f; R[6]=0.f;R[7]=0.f;R[8]=1.f;
        } else {
            float sc = c_scale[s];
            float r0 = sc * tanhf(a.prm[s][p*3+0]);
            float r1 = sc * tanhf(a.prm[s][p*3+1]);
            float r2 = sc * tanhf(a.prm[s][p*3+2]);
            float ang = sqrtf(r0*r0 + r1*r1 + r2*r2 + 1e-16f);
            float inv = 1.0f / ang;
            float ax = r0*inv, ay = r1*inv, az = r2*inv;
            float sn = sinf(ang), cs = cosf(ang), omc = 1.0f - cs;
            R[0] = cs + omc*ax*ax;      R[1] = omc*ax*ay - sn*az;  R[2] = omc*ax*az + sn*ay;
            R[3] = omc*ax*ay + sn*az;   R[4] = cs + omc*ay*ay;     R[5] = omc*ay*az - sn*ax;
            R[6] = omc*ax*az - sn*ay;   R[7] = omc*ay*az + sn*ax;  R[8] = cs + omc*az*az;
        }
        int par = c_parents[j];
        float rel0 = a.joints[j*3+0], rel1 = a.joints[j*3+1], rel2 = a.joints[j*3+2];
        if (par >= 0) { rel0 -= a.joints[par*3+0]; rel1 -= a.joints[par*3+1]; rel2 -= a.joints[par*3+2]; }
        R[9] = rel0; R[10] = rel1; R[11] = rel2;
    }
    __syncthreads();

    if (t < P_POSES) {
        int pp = t;
        for (int jj = 0; jj < NUM_J; jj++) {
            const float* R = sR[pp][jj];
            float* G = sG[pp][jj];
            if (jj == 0) {
                for (int m = 0; m < 12; m++) G[m] = R[m];
            } else {
                const float* Gp = sG[pp][c_parents[jj]];
                for (int r = 0; r < 3; r++)
                    for (int c = 0; c < 3; c++)
                        G[r*3+c] = Gp[r*3+0]*R[0*3+c] + Gp[r*3+1]*R[1*3+c] + Gp[r*3+2]*R[2*3+c];
                for (int r = 0; r < 3; r++)
                    G[9+r] = Gp[r*3+0]*R[9] + Gp[r*3+1]*R[10] + Gp[r*3+2]*R[11] + Gp[9+r];
            }
        }
    }
    __syncthreads();

    if (t < P_POSES * NUM_J) {
        const float* G = sG[p][j];
        float sh0 = sSh[p][0], sh1 = sSh[p][1], sh2 = sSh[p][2];

        a.outJ[(p*NUM_J + j)*3 + 0] = G[9]  + sh0;
        a.outJ[(p*NUM_J + j)*3 + 1] = G[10] + sh1;
        a.outJ[(p*NUM_J + j)*3 + 2] = G[11] + sh2;

        float jr0 = a.joints[j*3+0], jr1 = a.joints[j*3+1], jr2 = a.joints[j*3+2];
        float tt[3];
        tt[0] = G[9]  - (G[0]*jr0 + G[1]*jr1 + G[2]*jr2) + sh0;
        tt[1] = G[10] - (G[3]*jr0 + G[4]*jr1 + G[5]*jr2) + sh1;
        tt[2] = G[11] - (G[6]*jr0 + G[7]*jr1 + G[8]*jr2) + sh2;

        int baseA = ((p >> 1) * NUM_J + j) * 24 + (p & 1);
        for (int i = 0; i < 3; i++) {
            for (int k = 0; k < 3; k++)
                g_A[baseA + (i*4 + k) * 2] = G[i*3 + k];
            g_A[baseA + (i*4 + 3) * 2] = tt[i];
        }
    }
}

// ---------------------------------------------------------------------------
// Kernel 2: 4 adjacent vertices per thread; 2 pose-pairs per pass (4 passes).
// A read via broadcast LDG.128 from L1-hot g_A (off the smem crossbar);
// weights in smem as per-thread float4 (1 LDS.128 per joint per pass).
// ---------------------------------------------------------------------------
__global__ __launch_bounds__(BLK, 4) void lbs_main(const float* __restrict__ verts,
                                                   const float* __restrict__ weights,
                                                   float* __restrict__ out, int V) {
    __shared__ float4 sW4[NUM_J][BLK];   // [j][tid] = weights of verts 4tid..4tid+3  (47104 B)

    int tid  = threadIdx.x;
    int base = blockIdx.x * VPB;
    int nvb  = min(VPB, V - base);

    // ---- stage weights (transpose [v][j] -> [j][vquad]) ----
    {
        float* sWf = (float*)sW4;
        const float4* src = (const float4*)(weights + (size_t)base * NUM_J);
        int n4 = (nvb * NUM_J) >> 2;     // nvb % 4 == 0 -> exact
        for (int i = tid; i < n4; i += BLK) {
            float4 f = src[i];
            int e  = 4 * i;
            int vl = e / NUM_J;
            int j  = e - vl * NUM_J;
            float vals[4] = {f.x, f.y, f.z, f.w};
#pragma unroll
            for (int k = 0; k < 4; k++) {
                sWf[(j * BLK + (vl >> 2)) * 4 + (vl & 3)] = vals[k];
                if (++j == NUM_J) { j = 0; vl++; }
            }
        }
    }
    __syncthreads();

    int v0 = base + VT * tid;
    if (v0 >= V) return;   // all-or-nothing: V % 4 == 0

    // ---- vertex coords (3 x LDG.128, 48B-aligned since v0 % 4 == 0) ----
    float x[4], y[4], z[4];
    {
        const float4* vv = (const float4*)(verts + (size_t)v0 * 3);
        float4 f0 = vv[0], f1 = vv[1], f2 = vv[2];
        x[0]=f0.x; y[0]=f0.y; z[0]=f0.z;
        x[1]=f0.w; y[1]=f1.x; z[1]=f1.y;
        x[2]=f1.z; y[2]=f1.w; z[2]=f2.x;
        x[3]=f2.y; y[3]=f2.z; z[3]=f2.w;
    }
    ull x2[4], y2[4], z2[4];
#pragma unroll
    for (int v = 0; v < 4; v++) {
        x2[v] = packf2(x[v], x[v]);
        y2[v] = packf2(y[v], y[v]);
        z2[v] = packf2(z[v], z[v]);
    }

    size_t V3 = (size_t)V * 3;

#pragma unroll 1
    for (int pass = 0; pass < 4; pass++) {
        const ulonglong2* aA = ((const ulonglong2*)g_A) + (2*pass)   * (NUM_J * 6);
        const ulonglong2* aB = ((const ulonglong2*)g_A) + (2*pass+1) * (NUM_J * 6);

        ull accA[12], accB[12];
#pragma unroll
        for (int m = 0; m < 12; m++) { accA[m] = 0ull; accB[m] = 0ull; }

#pragma unroll 1
        for (int j = 0; j < NUM_J; j++) {
            float4 wq = sW4[j][tid];
            ull w2[4];
            w2[0] = packf2(wq.x, wq.x);
            w2[1] = packf2(wq.y, wq.y);
            w2[2] = packf2(wq.z, wq.z);
            w2[3] = packf2(wq.w, wq.w);

            {
                ulonglong2 q0 = __ldg(&aA[j*6+0]), q1 = __ldg(&aA[j*6+1]);
                ulonglong2 q2 = __ldg(&aA[j*6+2]), q3 = __ldg(&aA[j*6+3]);
                ulonglong2 q4 = __ldg(&aA[j*6+4]), q5 = __ldg(&aA[j*6+5]);
#pragma unroll
                for (int v = 0; v < 4; v++) {
                    ull u;
                    u = fma2(x2[v], q0.x, fma2(y2[v], q0.y, fma2(z2[v], q1.x, q1.y)));
                    accA[v*3+0] = fma2(w2[v], u, accA[v*3+0]);
                    u = fma2(x2[v], q2.x, fma2(y2[v], q2.y, fma2(z2[v], q3.x, q3.y)));
                    accA[v*3+1] = fma2(w2[v], u, accA[v*3+1]);
                    u = fma2(x2[v], q4.x, fma2(y2[v], q4.y, fma2(z2[v], q5.x, q5.y)));
                    accA[v*3+2] = fma2(w2[v], u, accA[v*3+2]);
                }
            }
            {
                ulonglong2 q0 = __ldg(&aB[j*6+0]), q1 = __ldg(&aB[j*6+1]);
                ulonglong2 q2 = __ldg(&aB[j*6+2]), q3 = __ldg(&aB[j*6+3]);
                ulonglong2 q4 = __ldg(&aB[j*6+4]), q5 = __ldg(&aB[j*6+5]);
#pragma unroll
                for (int v = 0; v < 4; v++) {
                    ull u;
                    u = fma2(x2[v], q0.x, fma2(y2[v], q0.y, fma2(z2[v], q1.x, q1.y)));
                    accB[v*3+0] = fma2(w2[v], u, accB[v*3+0]);
                    u = fma2(x2[v], q2.x, fma2(y2[v], q2.y, fma2(z2[v], q3.x, q3.y)));
                    accB[v*3+1] = fma2(w2[v], u, accB[v*3+1]);
                    u = fma2(x2[v], q4.x, fma2(y2[v], q4.y, fma2(z2[v], q5.x, q5.y)));
                    accB[v*3+2] = fma2(w2[v], u, accB[v*3+2]);
                }
            }
        }

        // ---- stores: 4 poses x 4 verts x 3 floats, each pose contiguous 48B ----
        float lA[12], hA[12], lB[12], hB[12];
#pragma unroll
        for (int m = 0; m < 12; m++) {
            unpackf2(accA[m], lA[m], hA[m]);
            unpackf2(accB[m], lB[m], hB[m]);
        }
        float* base0 = out + (size_t)(4*pass) * V3 + (size_t)v0 * 3;
        float4* p0 = (float4*)(base0);            // pose 4*pass+0
        float4* p1 = (float4*)(base0 + V3);       // pose 4*pass+1
        float4* p2 = (float4*)(base0 + 2*V3);     // pose 4*pass+2
        float4* p3 = (float4*)(base0 + 3*V3);     // pose 4*pass+3
        p0[0] = make_float4(lA[0], lA[1], lA[2], lA[3]);
        p0[1] = make_float4(lA[4], lA[5], lA[6], lA[7]);
        p0[2] = make_float4(lA[8], lA[9], lA[10], lA[11]);
        p1[0] = make_float4(hA[0], hA[1], hA[2], hA[3]);
        p1[1] = make_float4(hA[4], hA[5], hA[6], hA[7]);
        p1[2] = make_float4(hA[8], hA[9], hA[10], hA[11]);
        p2[0] = make_float4(lB[0], lB[1], lB[2], lB[3]);
        p2[1] = make_float4(lB[4], lB[5], lB[6], lB[7]);
        p2[2] = make_float4(lB[8], lB[9], lB[10], lB[11]);
        p3[0] = make_float4(hB[0], hB[1], hB[2], hB[3]);
        p3[1] = make_float4(hB[4], hB[5], hB[6], hB[7]);
        p3[2] = make_float4(hB[8], hB[9], hB[10], hB[11]);
    }
}

// ---------------------------------------------------------------------------
extern "C" void kernel_launch(void* const* d_in, const int* in_sizes, int n_in,
                              void* d_out, int out_size) {
    const float* vertices = (const float*)d_in[0];   // (1,V,3)
    const float* joints   = (const float*)d_in[1];   // (1,23,3)
    const float* weights  = (const float*)d_in[2];   // (V,23)
    const float* disp     = (const float*)d_in[3];   // (16,1,3)
    const float* rnd      = (const float*)d_in[4];   // (16,3)

    int V = in_sizes[0] / 3;
    float* out = (float*)d_out;

    SetupArgs sa;
    sa.joints = joints;
    sa.disp   = disp;
    sa.rnd    = rnd;
    for (int i = 0; i < 11; i++) sa.prm[i] = (const float*)d_in[5 + i];
    sa.outJ = out + (size_t)P_POSES * V * 3;

    lbs_setup<<<1, 384>>>(sa);

    int blocks = (V + VPB - 1) / VPB;
    lbs_main<<<blocks, BLK>>>(vertices, weights, out, V);
}

// round 5
// speedup vs baseline: 1.0671x; 1.0169x over previous
#include <cuda_runtime.h>
#include <math.h>

#define NUM_J 23
#define P_POSES 16
#define BLK 128
#define VT 4
#define VPB (VT*BLK)   // 512 vertices per block

typedef unsigned long long ull;

// Pose-pair interleaved A matrices: [pp(8)][j(23)][m(12)][pose_parity(2)] floats
__device__ __align__(16) float g_A[8 * NUM_J * 24];

__device__ __forceinline__ ull fma2(ull a, ull b, ull c) {
    ull d;
    asm("fma.rn.f32x2 %0, %1, %2, %3;" : "=l"(d) : "l"(a), "l"(b), "l"(c));
    return d;
}
__device__ __forceinline__ ull packf2(float lo, float hi) {
    ull r;
    asm("mov.b64 %0, {%1, %2};" : "=l"(r) : "f"(lo), "f"(hi));
    return r;
}
__device__ __forceinline__ void unpackf2(ull v, float& lo, float& hi) {
    asm("mov.b64 {%0, %1}, %2;" : "=f"(lo), "=f"(hi) : "l"(v));
}

// ---------------------------------------------------------------------------
// Kernel 1: setup (parallelized, 1 block x 384 threads).
// ---------------------------------------------------------------------------
struct SetupArgs {
    const float* joints;    // (23,3)
    const float* disp;      // (16,1,3)
    const float* rnd;       // (16,3)
    const float* prm[11];   // each (16,3)
    float* outJ;            // -> d_out + 16*V*3
};

__device__ const int   c_parents[NUM_J] = {-1,0,1,1,3,4,5,4,7,4,9,1,11,12,13,12,15,12,17,0,19,0,21};
__device__ const int   c_slot[NUM_J]    = { 0,-1,-1,1,2,3,-1,4,-1,5,-1,6,7,8,-1,9,-1,10,-1,-1,-1,-1,-1};
__device__ const float c_scale[11]      = {0.7853981633974483f, 1.5707963267948966f, 1.5707963267948966f,
                                           0.7853981633974483f, 0.7853981633974483f, 0.7853981633974483f,
                                           1.5707963267948966f, 1.5707963267948966f, 0.7853981633974483f,
                                           0.7853981633974483f, 0.7853981633974483f};

__global__ void lbs_setup(SetupArgs a) {
    __shared__ float sR[P_POSES][NUM_J][12];
    __shared__ float sG[P_POSES][NUM_J][12];
    __shared__ float sSh[P_POSES][3];

    int t = threadIdx.x;
    int p = t / NUM_J;
    int j = t - p * NUM_J;

    if (t < P_POSES) {
        sSh[t][0] = a.rnd[t*3+0] + 3.0f * tanhf(a.disp[t*3+0]);
        sSh[t][1] = a.rnd[t*3+1] + 3.0f * tanhf(a.disp[t*3+1]);
        sSh[t][2] = a.rnd[t*3+2] + 3.0f * tanhf(a.disp[t*3+2]);
    }
    if (t < P_POSES * NUM_J) {
        float* R = sR[p][j];
        int s = c_slot[j];
        if (s < 0) {
            R[0]=1.f;R[1]=0.f;R[2]=0.f; R[3]=0.f;R[4]=1.f;R[5]=0.f; R[6]=0.f;R[7]=0.f;R[8]=1.f;
        } else {
            float sc = c_scale[s];
            float r0 = sc * tanhf(a.prm[s][p*3+0]);
            float r1 = sc * tanhf(a.prm[s][p*3+1]);
            float r2 = sc * tanhf(a.prm[s][p*3+2]);
            float ang = sqrtf(r0*r0 + r1*r1 + r2*r2 + 1e-16f);
            float inv = 1.0f / ang;
            float ax = r0*inv, ay = r1*inv, az = r2*inv;
            float sn = sinf(ang), cs = cosf(ang), omc = 1.0f - cs;
            R[0] = cs + omc*ax*ax;      R[1] = omc*ax*ay - sn*az;  R[2] = omc*ax*az + sn*ay;
            R[3] = omc*ax*ay + sn*az;   R[4] = cs + omc*ay*ay;     R[5] = omc*ay*az - sn*ax;
            R[6] = omc*ax*az - sn*ay;   R[7] = omc*ay*az + sn*ax;  R[8] = cs + omc*az*az;
        }
        int par = c_parents[j];
        float rel0 = a.joints[j*3+0], rel1 = a.joints[j*3+1], rel2 = a.joints[j*3+2];
        if (par >= 0) { rel0 -= a.joints[par*3+0]; rel1 -= a.joints[par*3+1]; rel2 -= a.joints[par*3+2]; }
        R[9] = rel0; R[10] = rel1; R[11] = rel2;
    }
    __syncthreads();

    if (t < P_POSES) {
        int pp = t;
        for (int jj = 0; jj < NUM_J; jj++) {
            const float* R = sR[pp][jj];
            float* G = sG[pp][jj];
            if (jj == 0) {
                for (int m = 0; m < 12; m++) G[m] = R[m];
            } else {
                const float* Gp = sG[pp][c_parents[jj]];
                for (int r = 0; r < 3; r++)
                    for (int c = 0; c < 3; c++)
                        G[r*3+c] = Gp[r*3+0]*R[0*3+c] + Gp[r*3+1]*R[1*3+c] + Gp[r*3+2]*R[2*3+c];
                for (int r = 0; r < 3; r++)
                    G[9+r] = Gp[r*3+0]*R[9] + Gp[r*3+1]*R[10] + Gp[r*3+2]*R[11] + Gp[9+r];
            }
        }
    }
    __syncthreads();

    if (t < P_POSES * NUM_J) {
        const float* G = sG[p][j];
        float sh0 = sSh[p][0], sh1 = sSh[p][1], sh2 = sSh[p][2];

        a.outJ[(p*NUM_J + j)*3 + 0] = G[9]  + sh0;
        a.outJ[(p*NUM_J + j)*3 + 1] = G[10] + sh1;
        a.outJ[(p*NUM_J + j)*3 + 2] = G[11] + sh2;

        float jr0 = a.joints[j*3+0], jr1 = a.joints[j*3+1], jr2 = a.joints[j*3+2];
        float tt[3];
        tt[0] = G[9]  - (G[0]*jr0 + G[1]*jr1 + G[2]*jr2) + sh0;
        tt[1] = G[10] - (G[3]*jr0 + G[4]*jr1 + G[5]*jr2) + sh1;
        tt[2] = G[11] - (G[6]*jr0 + G[7]*jr1 + G[8]*jr2) + sh2;

        int baseA = ((p >> 1) * NUM_J + j) * 24 + (p & 1);
        for (int i = 0; i < 3; i++) {
            for (int k = 0; k < 3; k++)
                g_A[baseA + (i*4 + k) * 2] = G[i*3 + k];
            g_A[baseA + (i*4 + 3) * 2] = tt[i];
        }
    }
}

// ---------------------------------------------------------------------------
// Kernel 2: 4 adjacent vertices per thread; 2 pose-pairs per pass (4 passes).
// A read via broadcast LDG.128 from L1-hot g_A (off the smem crossbar);
// weights in smem as per-thread float4 (1 LDS.128 per joint per pass).
// ---------------------------------------------------------------------------
__global__ __launch_bounds__(BLK, 4) void lbs_main(const float* __restrict__ verts,
                                                   const float* __restrict__ weights,
                                                   float* __restrict__ out, int V) {
    __shared__ float4 sW4[NUM_J][BLK];   // [j][tid] = weights of verts 4tid..4tid+3  (47104 B)

    int tid  = threadIdx.x;
    int base = blockIdx.x * VPB;
    int nvb  = min(VPB, V - base);

    // ---- stage weights (transpose [v][j] -> [j][vquad]) ----
    {
        float* sWf = (float*)sW4;
        const float4* src = (const float4*)(weights + (size_t)base * NUM_J);
        int n4 = (nvb * NUM_J) >> 2;     // nvb % 4 == 0 -> exact
        for (int i = tid; i < n4; i += BLK) {
            float4 f = src[i];
            int e  = 4 * i;
            int vl = e / NUM_J;
            int j  = e - vl * NUM_J;
            float vals[4] = {f.x, f.y, f.z, f.w};
#pragma unroll
            for (int k = 0; k < 4; k++) {
                sWf[(j * BLK + (vl >> 2)) * 4 + (vl & 3)] = vals[k];
                if (++j == NUM_J) { j = 0; vl++; }
            }
        }
    }
    __syncthreads();

    int v0 = base + VT * tid;
    if (v0 >= V) return;   // all-or-nothing: V % 4 == 0

    // ---- vertex coords (3 x LDG.128, 48B-aligned since v0 % 4 == 0) ----
    float x[4], y[4], z[4];
    {
        const float4* vv = (const float4*)(verts + (size_t)v0 * 3);
        float4 f0 = vv[0], f1 = vv[1], f2 = vv[2];
        x[0]=f0.x; y[0]=f0.y; z[0]=f0.z;
        x[1]=f0.w; y[1]=f1.x; z[1]=f1.y;
        x[2]=f1.z; y[2]=f1.w; z[2]=f2.x;
        x[3]=f2.y; y[3]=f2.z; z[3]=f2.w;
    }
    ull x2[4], y2[4], z2[4];
#pragma unroll
    for (int v = 0; v < 4; v++) {
        x2[v] = packf2(x[v], x[v]);
        y2[v] = packf2(y[v], y[v]);
        z2[v] = packf2(z[v], z[v]);
    }

    size_t V3 = (size_t)V * 3;

#pragma unroll 1
    for (int pass = 0; pass < 4; pass++) {
        const ulonglong2* aA = ((const ulonglong2*)g_A) + (2*pass)   * (NUM_J * 6);
        const ulonglong2* aB = ((const ulonglong2*)g_A) + (2*pass+1) * (NUM_J * 6);

        ull accA[12], accB[12];
#pragma unroll
        for (int m = 0; m < 12; m++) { accA[m] = 0ull; accB[m] = 0ull; }

#pragma unroll 1
        for (int j = 0; j < NUM_J; j++) {
            float4 wq = sW4[j][tid];
            ull w2[4];
            w2[0] = packf2(wq.x, wq.x);
            w2[1] = packf2(wq.y, wq.y);
            w2[2] = packf2(wq.z, wq.z);
            w2[3] = packf2(wq.w, wq.w);

            {
                ulonglong2 q0 = __ldg(&aA[j*6+0]), q1 = __ldg(&aA[j*6+1]);
                ulonglong2 q2 = __ldg(&aA[j*6+2]), q3 = __ldg(&aA[j*6+3]);
                ulonglong2 q4 = __ldg(&aA[j*6+4]), q5 = __ldg(&aA[j*6+5]);
#pragma unroll
                for (int v = 0; v < 4; v++) {
                    ull u;
                    u = fma2(x2[v], q0.x, fma2(y2[v], q0.y, fma2(z2[v], q1.x, q1.y)));
                    accA[v*3+0] = fma2(w2[v], u, accA[v*3+0]);
                    u = fma2(x2[v], q2.x, fma2(y2[v], q2.y, fma2(z2[v], q3.x, q3.y)));
                    accA[v*3+1] = fma2(w2[v], u, accA[v*3+1]);
                    u = fma2(x2[v], q4.x, fma2(y2[v], q4.y, fma2(z2[v], q5.x, q5.y)));
                    accA[v*3+2] = fma2(w2[v], u, accA[v*3+2]);
                }
            }
            {
                ulonglong2 q0 = __ldg(&aB[j*6+0]), q1 = __ldg(&aB[j*6+1]);
                ulonglong2 q2 = __ldg(&aB[j*6+2]), q3 = __ldg(&aB[j*6+3]);
                ulonglong2 q4 = __ldg(&aB[j*6+4]), q5 = __ldg(&aB[j*6+5]);
#pragma unroll
                for (int v = 0; v < 4; v++) {
                    ull u;
                    u = fma2(x2[v], q0.x, fma2(y2[v], q0.y, fma2(z2[v], q1.x, q1.y)));
                    accB[v*3+0] = fma2(w2[v], u, accB[v*3+0]);
                    u = fma2(x2[v], q2.x, fma2(y2[v], q2.y, fma2(z2[v], q3.x, q3.y)));
                    accB[v*3+1] = fma2(w2[v], u, accB[v*3+1]);
                    u = fma2(x2[v], q4.x, fma2(y2[v], q4.y, fma2(z2[v], q5.x, q5.y)));
                    accB[v*3+2] = fma2(w2[v], u, accB[v*3+2]);
                }
            }
        }

        // ---- stores: 4 poses x 4 verts x 3 floats, each pose contiguous 48B ----
        float lA[12], hA[12], lB[12], hB[12];
#pragma unroll
        for (int m = 0; m < 12; m++) {
            unpackf2(accA[m], lA[m], hA[m]);
            unpackf2(accB[m], lB[m], hB[m]);
        }
        float* base0 = out + (size_t)(4*pass) * V3 + (size_t)v0 * 3;
        float4* p0 = (float4*)(base0);            // pose 4*pass+0
        float4* p1 = (float4*)(base0 + V3);       // pose 4*pass+1
        float4* p2 = (float4*)(base0 + 2*V3);     // pose 4*pass+2
        float4* p3 = (float4*)(base0 + 3*V3);     // pose 4*pass+3
        p0[0] = make_float4(lA[0], lA[1], lA[2], lA[3]);
        p0[1] = make_float4(lA[4], lA[5], lA[6], lA[7]);
        p0[2] = make_float4(lA[8], lA[9], lA[10], lA[11]);
        p1[0] = make_float4(hA[0], hA[1], hA[2], hA[3]);
        p1[1] = make_float4(hA[4], hA[5], hA[6], hA[7]);
        p1[2] = make_float4(hA[8], hA[9], hA[10], hA[11]);
        p2[0] = make_float4(lB[0], lB[1], lB[2], lB[3]);
        p2[1] = make_float4(lB[4], lB[5], lB[6], lB[7]);
        p2[2] = make_float4(lB[8], lB[9], lB[10], lB[11]);
        p3[0] = make_float4(hB[0], hB[1], hB[2], hB[3]);
        p3[1] = make_float4(hB[4], hB[5], hB[6], hB[7]);
        p3[2] = make_float4(hB[8], hB[9], hB[10], hB[11]);
    }
}

// ---------------------------------------------------------------------------
extern "C" void kernel_launch(void* const* d_in, const int* in_sizes, int n_in,
                              void* d_out, int out_size) {
    const float* vertices = (const float*)d_in[0];   // (1,V,3)
    const float* joints   = (const float*)d_in[1];   // (1,23,3)
    const float* weights  = (const float*)d_in[2];   // (V,23)
    const float* disp     = (const float*)d_in[3];   // (16,1,3)
    const float* rnd      = (const float*)d_in[4];   // (16,3)

    int V = in_sizes[0] / 3;
    float* out = (float*)d_out;

    SetupArgs sa;
    sa.joints = joints;
    sa.disp   = disp;
    sa.rnd    = rnd;
    for (int i = 0; i < 11; i++) sa.prm[i] = (const float*)d_in[5 + i];
    sa.outJ = out + (size_t)P_POSES * V * 3;

    lbs_setup<<<1, 384>>>(sa);

    int blocks = (V + VPB - 1) / VPB;
    lbs_main<<<blocks, BLK>>>(vertices, weights, out, V);
}

// round 7
// speedup vs baseline: 1.4487x; 1.3576x over previous
#include <cuda_runtime.h>
#include <cuda_bf16.h>
#include <math.h>
#include <stdint.h>

#define NUM_J 23
#define NP 16
#define NT 128
#define THREADS 256

#define SA_STRIDE_B 208                  // bytes per A row in smem (104 bf16, padded)
#define A_BYTES (48 * SA_STRIDE_B)       // 9984
#define OFF_AH 0
#define OFF_AL A_BYTES                   // 9984
#define OFF_W  (2 * A_BYTES)             // 19968  float [128][23]
#define OFF_V  (OFF_W + 128*23*4)        // 31744  float4 [128] = (x,y,z,1)
#define SMEM_TOTAL (OFF_V + 128*16)      // 33792
#define POSE_STRIDE 400                  // floats per pose in epilogue buffer (16*400*4=25600B)

// M images, bf16 hi/lo, row-major [48 rows][48 u32-words] (2 bf16/word, K=96).
// Words 46,47 (j=23 pad) are never written -> stay zero.
__device__ uint32_t g_Ahi[48 * 48];
__device__ uint32_t g_Alo[48 * 48];

// ---------------- helpers ----------------
__device__ __forceinline__ uint32_t smem_u32(const void* p) {
    uint32_t a;
    asm("{ .reg .u64 t; cvta.to.shared.u64 t, %1; cvt.u32.u64 %0, t; }" : "=r"(a) : "l"(p));
    return a;
}
__device__ __forceinline__ uint32_t pk2(float lo, float hi) {   // lo -> low 16 bits
    __nv_bfloat162 t = __floats2bfloat162_rn(lo, hi);
    return *reinterpret_cast<uint32_t*>(&t);
}
__device__ __forceinline__ uint32_t cvt2(float lo, float hi) {  // lo -> low half
    uint32_t r;
    asm("cvt.rn.bf16x2.f32 %0, %1, %2;" : "=r"(r) : "f"(hi), "f"(lo));
    return r;
}
__device__ __forceinline__ void split_bf(float v, float& h, float& l) {
    h = __bfloat162float(__float2bfloat16_rn(v));
    l = v - h;
}
__device__ __forceinline__ void ldmA(uint32_t& a0, uint32_t& a1, uint32_t& a2, uint32_t& a3,
                                     uint32_t addr) {
    asm volatile("ldmatrix.sync.aligned.m8n8.x4.shared.b16 {%0,%1,%2,%3}, [%4];"
                 : "=r"(a0), "=r"(a1), "=r"(a2), "=r"(a3) : "r"(addr));
}
__device__ __forceinline__ void mma16816(float (&d)[4],
                                         uint32_t a0, uint32_t a1, uint32_t a2, uint32_t a3,
                                         uint32_t b0, uint32_t b1) {
    asm volatile("mma.sync.aligned.m16n8k16.row.col.f32.bf16.bf16.f32 "
                 "{%0,%1,%2,%3}, {%4,%5,%6,%7}, {%8,%9}, {%0,%1,%2,%3};"
                 : "+f"(d[0]), "+f"(d[1]), "+f"(d[2]), "+f"(d[3])
                 : "r"(a0), "r"(a1), "r"(a2), "r"(a3), "r"(b0), "r"(b1));
}

// ---------------------------------------------------------------------------
// Kernel 1: setup (1 block x 384 threads). Builds M = A-affine (shift folded,
// valid since weight rows sum to 1), splits to bf16 hi/lo, writes posed joints.
// ---------------------------------------------------------------------------
struct SetupArgs {
    const float* joints;
    const float* disp;
    const float* rnd;
    const float* prm[11];
    float* outJ;
};

__device__ const int   c_parents[NUM_J] = {-1,0,1,1,3,4,5,4,7,4,9,1,11,12,13,12,15,12,17,0,19,0,21};
__device__ const int   c_slot[NUM_J]    = { 0,-1,-1,1,2,3,-1,4,-1,5,-1,6,7,8,-1,9,-1,10,-1,-1,-1,-1,-1};
__device__ const float c_scale[11]      = {0.7853981633974483f, 1.5707963267948966f, 1.5707963267948966f,
                                           0.7853981633974483f, 0.7853981633974483f, 0.7853981633974483f,
                                           1.5707963267948966f, 1.5707963267948966f, 0.7853981633974483f,
                                           0.7853981633974483f, 0.7853981633974483f};

__global__ void lbs_setup(SetupArgs a) {
    __shared__ float sR[NP][NUM_J][12];
    __shared__ float sG[NP][NUM_J][12];
    __shared__ float sSh[NP][3];

    int t = threadIdx.x;
    int p = t / NUM_J;
    int j = t - p * NUM_J;

    if (t < NP) {
        sSh[t][0] = a.rnd[t*3+0] + 3.0f * tanhf(a.disp[t*3+0]);
        sSh[t][1] = a.rnd[t*3+1] + 3.0f * tanhf(a.disp[t*3+1]);
        sSh[t][2] = a.rnd[t*3+2] + 3.0f * tanhf(a.disp[t*3+2]);
    }
    if (t < NP * NUM_J) {
        float* R = sR[p][j];
        int s = c_slot[j];
        if (s < 0) {
            R[0]=1.f;R[1]=0.f;R[2]=0.f; R[3]=0.f;R[4]=1.f;R[5]=0.f; R[6]=0.f;R[7]=0.f;R[8]=1.f;
        } else {
            float sc = c_scale[s];
            float r0 = sc * tanhf(a.prm[s][p*3+0]);
            float r1 = sc * tanhf(a.prm[s][p*3+1]);
            float r2 = sc * tanhf(a.prm[s][p*3+2]);
            float ang = sqrtf(r0*r0 + r1*r1 + r2*r2 + 1e-16f);
            float inv = 1.0f / ang;
            float ax = r0*inv, ay = r1*inv, az = r2*inv;
            float sn = sinf(ang), cs = cosf(ang), omc = 1.0f - cs;
            R[0] = cs + omc*ax*ax;      R[1] = omc*ax*ay - sn*az;  R[2] = omc*ax*az + sn*ay;
            R[3] = omc*ax*ay + sn*az;   R[4] = cs + omc*ay*ay;     R[5] = omc*ay*az - sn*ax;
            R[6] = omc*ax*az - sn*ay;   R[7] = omc*ay*az + sn*ax;  R[8] = cs + omc*az*az;
        }
        int par = c_parents[j];
        float rel0 = a.joints[j*3+0], rel1 = a.joints[j*3+1], rel2 = a.joints[j*3+2];
        if (par >= 0) { rel0 -= a.joints[par*3+0]; rel1 -= a.joints[par*3+1]; rel2 -= a.joints[par*3+2]; }
        R[9] = rel0; R[10] = rel1; R[11] = rel2;
    }
    __syncthreads();

    if (t < NP) {
        for (int jj = 0; jj < NUM_J; jj++) {
            const float* R = sR[t][jj];
            float* G = sG[t][jj];
            if (jj == 0) {
                for (int m = 0; m < 12; m++) G[m] = R[m];
            } else {
                const float* Gp = sG[t][c_parents[jj]];
                for (int r = 0; r < 3; r++)
                    for (int c = 0; c < 3; c++)
                        G[r*3+c] = Gp[r*3+0]*R[0*3+c] + Gp[r*3+1]*R[1*3+c] + Gp[r*3+2]*R[2*3+c];
                for (int r = 0; r < 3; r++)
                    G[9+r] = Gp[r*3+0]*R[9] + Gp[r*3+1]*R[10] + Gp[r*3+2]*R[11] + Gp[9+r];
            }
        }
    }
    __syncthreads();

    if (t < NP * NUM_J) {
        const float* G = sG[p][j];
        float sh0 = sSh[p][0], sh1 = sSh[p][1], sh2 = sSh[p][2];

        a.outJ[(p*NUM_J + j)*3 + 0] = G[9]  + sh0;
        a.outJ[(p*NUM_J + j)*3 + 1] = G[10] + sh1;
        a.outJ[(p*NUM_J + j)*3 + 2] = G[11] + sh2;

        float jr0 = a.joints[j*3+0], jr1 = a.joints[j*3+1], jr2 = a.joints[j*3+2];
        float tt[3];
        tt[0] = G[9]  - (G[0]*jr0 + G[1]*jr1 + G[2]*jr2) + sh0;
        tt[1] = G[10] - (G[3]*jr0 + G[4]*jr1 + G[5]*jr2) + sh1;
        tt[2] = G[11] - (G[6]*jr0 + G[7]*jr1 + G[8]*jr2) + sh2;

        // M rows m = 3p+i, K cols 4j..4j+3 = (R_i0, R_i1, R_i2, t_i)
        for (int i = 0; i < 3; i++) {
            int m = 3*p + i;
            float vals[4] = {G[i*3+0], G[i*3+1], G[i*3+2], tt[i]};
            float h[4], l[4];
            for (int c = 0; c < 4; c++) split_bf(vals[c], h[c], l[c]);
            g_Ahi[m*48 + 2*j + 0] = pk2(h[0], h[1]);
            g_Ahi[m*48 + 2*j + 1] = pk2(h[2], h[3]);
            g_Alo[m*48 + 2*j + 0] = pk2(l[0], l[1]);
            g_Alo[m*48 + 2*j + 1] = pk2(l[2], l[3]);
        }
    }
}

// ---------------------------------------------------------------------------
// Kernel 2: 128-vertex tile GEMM via mma.sync (bf16, hi/lo x3 passes).
// Warp w owns n8 tiles {2w, 2w+1} across all 3 m16 tiles (48 M-rows).
// B fragments computed in registers; A via ldmatrix from smem.
// ---------------------------------------------------------------------------
__global__ __launch_bounds__(THREADS) void lbs_mma(const float* __restrict__ verts,
                                                   const float* __restrict__ weights,
                                                   float* __restrict__ out, int V) {
    extern __shared__ __align__(16) char smem[];
    uint32_t sb = smem_u32(smem);
    float* sWf = (float*)(smem + OFF_W);
    float* sVf = (float*)(smem + OFF_V);

    int tid  = threadIdx.x;
    int lane = tid & 31;
    int warp = tid >> 5;
    int m4   = lane & 3;
    int grp  = lane >> 2;
    int v0   = blockIdx.x * NT;
    int nv   = min(NT, V - v0);

    // ---- stage A hi/lo (row-major, padded stride) ----
    for (int i = tid; i < 48*48; i += THREADS) {
        int m = i / 48, c = i - m*48;
        *(uint32_t*)(smem + OFF_AH + m*SA_STRIDE_B + c*4) = g_Ahi[i];
        *(uint32_t*)(smem + OFF_AL + m*SA_STRIDE_B + c*4) = g_Alo[i];
    }
    // ---- stage weights (float4, zero-fill tail) ----
    {
        const float4* src = (const float4*)(weights + (size_t)v0 * NUM_J);
        int wn4 = (nv * NUM_J) >> 2;     // nv*23 % 4 == 0 for nv in {128,32}
        for (int i = tid; i < (NT*NUM_J)/4; i += THREADS) {
            float4 f = make_float4(0.f, 0.f, 0.f, 0.f);
            if (i < wn4) f = __ldg(src + i);
            *(float4*)(sWf + i*4) = f;
        }
    }
    // ---- stage verts as (x,y,z,1), zeros beyond nv ----
    if (tid < NT) {
        sVf[tid*4 + 3] = 1.0f;
        if (tid >= nv) { sVf[tid*4+0] = 0.f; sVf[tid*4+1] = 0.f; sVf[tid*4+2] = 0.f; }
    }
    {
        int nf4 = (nv * 3) >> 2;
        if (tid < nf4) {
            float4 f = __ldg((const float4*)(verts + (size_t)v0*3) + tid);
            int e = tid * 4;
            sVf[(e/3)*4 + (e%3)] = f.x;
            sVf[((e+1)/3)*4 + ((e+1)%3)] = f.y;
            sVf[((e+2)/3)*4 + ((e+2)%3)] = f.z;
            sVf[((e+3)/3)*4 + ((e+3)%3)] = f.w;
        }
    }
    __syncthreads();

    // ldmatrix per-lane base offsets (A row-major 16x16 fragments)
    uint32_t aoff = (uint32_t)((lane & 15) * SA_STRIDE_B + ((lane >> 4) << 4));
    uint32_t aHi = sb + OFF_AH + aoff;
    uint32_t aLo = sb + OFF_AL + aoff;

    float d[2][3][4];
#pragma unroll
    for (int t = 0; t < 2; t++)
#pragma unroll
        for (int mt = 0; mt < 3; mt++)
#pragma unroll
            for (int q = 0; q < 4; q++) d[t][mt][q] = 0.f;

    int jbase = m4 >> 1;

#pragma unroll
    for (int t = 0; t < 2; t++) {
        int n8 = warp * 2 + t;
        int vB = n8 * 8 + grp;                 // B-fragment column vertex
        float4 vq = *(const float4*)(sVf + vB*4);
        float vc0 = (m4 & 1) ? vq.z : vq.x;
        float vc1 = (m4 & 1) ? vq.w : vq.y;
        const float* wrow = sWf + vB * NUM_J;

#pragma unroll
        for (int kb = 0; kb < 6; kb++) {
            int jl = 4*kb + jbase;
            int jh = jl + 2;
            float wl = wrow[jl];
            float wh = (jh < NUM_J) ? wrow[jh] : 0.f;
            float p0 = wl*vc0, p1 = wl*vc1, p2 = wh*vc0, p3 = wh*vc1;
            uint32_t bh0 = cvt2(p0, p1);
            uint32_t bh1 = cvt2(p2, p3);
            float h0 = __uint_as_float(bh0 << 16);
            float h1 = __uint_as_float(bh0 & 0xffff0000u);
            float h2 = __uint_as_float(bh1 << 16);
            float h3 = __uint_as_float(bh1 & 0xffff0000u);
            uint32_t bl0 = cvt2(p0 - h0, p1 - h1);
            uint32_t bl1 = cvt2(p2 - h2, p3 - h3);

#pragma unroll
            for (int mt = 0; mt < 3; mt++) {
                uint32_t a0, a1, a2, a3;
                ldmA(a0, a1, a2, a3, aHi + mt*16*SA_STRIDE_B + kb*32);
                mma16816(d[t][mt], a0, a1, a2, a3, bh0, bh1);   // Ah*Sh
                mma16816(d[t][mt], a0, a1, a2, a3, bl0, bl1);   // Ah*Sl
                ldmA(a0, a1, a2, a3, aLo + mt*16*SA_STRIDE_B + kb*32);
                mma16816(d[t][mt], a0, a1, a2, a3, bh0, bh1);   // Al*Sh
            }
        }
    }
    __syncthreads();

    // ---- epilogue: D -> smem in output layout [pose][v*3+i] ----
    float* sE = (float*)smem;
#pragma unroll
    for (int t = 0; t < 2; t++) {
        int vb = (warp*2 + t)*8 + 2*m4;        // D columns 2c, 2c+1
#pragma unroll
        for (int mt = 0; mt < 3; mt++) {
            int r0 = mt*16 + grp;
            int r1 = r0 + 8;
            int pA = r0/3, iA = r0 - 3*pA;
            int pB = r1/3, iB = r1 - 3*pB;
            sE[pA*POSE_STRIDE + vb*3     + iA] = d[t][mt][0];
            sE[pA*POSE_STRIDE + (vb+1)*3 + iA] = d[t][mt][1];
            sE[pB*POSE_STRIDE + vb*3     + iB] = d[t][mt][2];
            sE[pB*POSE_STRIDE + (vb+1)*3 + iB] = d[t][mt][3];
        }
    }
    __syncthreads();

    // ---- coalesced float4 copy out ----
    size_t V3 = (size_t)V * 3;
    int nf4 = (nv * 3) >> 2;                   // valid float4 per pose (96 or 24)
    for (int q = tid; q < NP * 96; q += THREADS) {
        int p = q / 96, r = q - p*96;
        if (r < nf4) {
            float4 val = *(const float4*)(sE + p*POSE_STRIDE + r*4);
            *(float4*)(out + (size_t)p*V3 + (size_t)v0*3 + r*4) = val;
        }
    }
}

// ---------------------------------------------------------------------------
extern "C" void kernel_launch(void* const* d_in, const int* in_sizes, int n_in,
                              void* d_out, int out_size) {
    const float* vertices = (const float*)d_in[0];   // (1,V,3)
    const float* joints   = (const float*)d_in[1];   // (1,23,3)
    const float* weights  = (const float*)d_in[2];   // (V,23)
    const float* disp     = (const float*)d_in[3];   // (16,1,3)
    const float* rnd      = (const float*)d_in[4];   // (16,3)

    int V = in_sizes[0] / 3;
    float* out = (float*)d_out;

    SetupArgs sa;
    sa.joints = joints;
    sa.disp   = disp;
    sa.rnd    = rnd;
    for (int i = 0; i < 11; i++) sa.prm[i] = (const float*)d_in[5 + i];
    sa.outJ = out + (size_t)NP * V * 3;

    lbs_setup<<<1, 384>>>(sa);
    int blocks = (V + NT - 1) / NT;
    lbs_mma<<<blocks, THREADS, SMEM_TOTAL>>>(vertices, weights, out, V);
}

// round 8
// speedup vs baseline: 1.8943x; 1.3076x over previous
#include <cuda_runtime.h>
#include <cuda_bf16.h>
#include <math.h>
#include <stdint.h>

#define NUM_J 23
#define NP 16
#define NT 192                 // vertices per CTA tile (8 warps x 3 n8-tiles x 8)
#define THREADS 256

#define SA_STRIDE_B 208        // bytes per A row in smem (104 bf16, padded)
#define A_BYTES (48 * SA_STRIDE_B)          // 9984
#define OFF_AH 0
#define OFF_AL A_BYTES                       // 9984
#define OFF_W  (2 * A_BYTES)                 // 19968: float [192][23] = 17664 B
#define OFF_V  (OFF_W + NT*NUM_J*4)          // 37632: float4 [192] = 3072 B
#define SMEM_TOTAL (OFF_V + NT*16)           // 40704
#define POSE_STRIDE 580                      // floats per pose in epilogue (192*3+4)
// epilogue needs 16*580*4 = 37120 <= 40704 (aliases A/W/V)

// M images, bf16 hi/lo, row-major [48 rows][48 u32-words] (2 bf16/word, K=96).
// Words 46,47 (j=23 pad) never written -> stay zero.
__device__ uint32_t g_Ahi[48 * 48];
__device__ uint32_t g_Alo[48 * 48];

// ---------------- helpers ----------------
__device__ __forceinline__ uint32_t smem_u32(const void* p) {
    uint32_t a;
    asm("{ .reg .u64 t; cvta.to.shared.u64 t, %1; cvt.u32.u64 %0, t; }" : "=r"(a) : "l"(p));
    return a;
}
__device__ __forceinline__ uint32_t pk2(float lo, float hi) {
    __nv_bfloat162 t = __floats2bfloat162_rn(lo, hi);
    return *reinterpret_cast<uint32_t*>(&t);
}
__device__ __forceinline__ uint32_t cvt2(float lo, float hi) {  // lo -> low half
    uint32_t r;
    asm("cvt.rn.bf16x2.f32 %0, %1, %2;" : "=r"(r) : "f"(hi), "f"(lo));
    return r;
}
__device__ __forceinline__ void split_bf(float v, float& h, float& l) {
    h = __bfloat162float(__float2bfloat16_rn(v));
    l = v - h;
}
__device__ __forceinline__ void ldmA(uint32_t& a0, uint32_t& a1, uint32_t& a2, uint32_t& a3,
                                     uint32_t addr) {
    asm volatile("ldmatrix.sync.aligned.m8n8.x4.shared.b16 {%0,%1,%2,%3}, [%4];"
                 : "=r"(a0), "=r"(a1), "=r"(a2), "=r"(a3) : "r"(addr));
}
__device__ __forceinline__ void mma16816(float (&d)[4],
                                         uint32_t a0, uint32_t a1, uint32_t a2, uint32_t a3,
                                         uint32_t b0, uint32_t b1) {
    asm volatile("mma.sync.aligned.m16n8k16.row.col.f32.bf16.bf16.f32 "
                 "{%0,%1,%2,%3}, {%4,%5,%6,%7}, {%8,%9}, {%0,%1,%2,%3};"
                 : "+f"(d[0]), "+f"(d[1]), "+f"(d[2]), "+f"(d[3])
                 : "r"(a0), "r"(a1), "r"(a2), "r"(a3), "r"(b0), "r"(b1));
}

// ---------------------------------------------------------------------------
// Kernel 1: setup. 512 threads: Rodrigues parallel over (p,j); kinematic chain
// warp-per-pose with 12 lanes computing the 12 G-elements per step; A-emit
// (shift folded; valid since weight rows sum to 1) + joints output parallel.
// ---------------------------------------------------------------------------
struct SetupArgs {
    const float* joints;
    const float* disp;
    const float* rnd;
    const float* prm[11];
    float* outJ;
};

__device__ const int   c_parents[NUM_J] = {-1,0,1,1,3,4,5,4,7,4,9,1,11,12,13,12,15,12,17,0,19,0,21};
__device__ const int   c_slot[NUM_J]    = { 0,-1,-1,1,2,3,-1,4,-1,5,-1,6,7,8,-1,9,-1,10,-1,-1,-1,-1,-1};
__device__ const float c_scale[11]      = {0.7853981633974483f, 1.5707963267948966f, 1.5707963267948966f,
                                           0.7853981633974483f, 0.7853981633974483f, 0.7853981633974483f,
                                           1.5707963267948966f, 1.5707963267948966f, 0.7853981633974483f,
                                           0.7853981633974483f, 0.7853981633974483f};

__global__ void lbs_setup(SetupArgs a) {
    __shared__ float sR[NP][NUM_J][12];
    __shared__ float sG[NP][NUM_J][12];
    __shared__ float sSh[NP][3];

    int t = threadIdx.x;
    int p = t / NUM_J;
    int j = t - p * NUM_J;

    if (t < NP) {
        sSh[t][0] = a.rnd[t*3+0] + 3.0f * tanhf(a.disp[t*3+0]);
        sSh[t][1] = a.rnd[t*3+1] + 3.0f * tanhf(a.disp[t*3+1]);
        sSh[t][2] = a.rnd[t*3+2] + 3.0f * tanhf(a.disp[t*3+2]);
    }
    if (t < NP * NUM_J) {
        float* R = sR[p][j];
        int s = c_slot[j];
        if (s < 0) {
            R[0]=1.f;R[1]=0.f;R[2]=0.f; R[3]=0.f;R[4]=1.f;R[5]=0.f; R[6]=0.f;R[7]=0.f;R[8]=1.f;
        } else {
            float sc = c_scale[s];
            float r0 = sc * tanhf(a.prm[s][p*3+0]);
            float r1 = sc * tanhf(a.prm[s][p*3+1]);
            float r2 = sc * tanhf(a.prm[s][p*3+2]);
            float ang = sqrtf(r0*r0 + r1*r1 + r2*r2 + 1e-16f);
            float inv = 1.0f / ang;
            float ax = r0*inv, ay = r1*inv, az = r2*inv;
            float sn = sinf(ang), cs = cosf(ang), omc = 1.0f - cs;
            R[0] = cs + omc*ax*ax;      R[1] = omc*ax*ay - sn*az;  R[2] = omc*ax*az + sn*ay;
            R[3] = omc*ax*ay + sn*az;   R[4] = cs + omc*ay*ay;     R[5] = omc*ay*az - sn*ax;
            R[6] = omc*ax*az - sn*ay;   R[7] = omc*ay*az + sn*ax;  R[8] = cs + omc*az*az;
        }
        int par = c_parents[j];
        float rel0 = a.joints[j*3+0], rel1 = a.joints[j*3+1], rel2 = a.joints[j*3+2];
        if (par >= 0) { rel0 -= a.joints[par*3+0]; rel1 -= a.joints[par*3+1]; rel2 -= a.joints[par*3+2]; }
        R[9] = rel0; R[10] = rel1; R[11] = rel2;
    }
    __syncthreads();

    // warp-per-pose chain: lane m computes G element m each step
    {
        int wp = t >> 5, lane = t & 31;
        if (wp < NP) {
#pragma unroll 1
            for (int jj = 0; jj < NUM_J; jj++) {
                if (lane < 12) {
                    const float* Rj = sR[wp][jj];
                    float G;
                    if (jj == 0) {
                        G = Rj[lane];
                    } else {
                        const float* Gp = sG[wp][c_parents[jj]];
                        if (lane < 9) {
                            int r = lane / 3, c = lane - 3*(lane/3);
                            G = Gp[r*3+0]*Rj[c] + Gp[r*3+1]*Rj[3+c] + Gp[r*3+2]*Rj[6+c];
                        } else {
                            int r = lane - 9;
                            G = Gp[r*3+0]*Rj[9] + Gp[r*3+1]*Rj[10] + Gp[r*3+2]*Rj[11] + Gp[9+r];
                        }
                    }
                    sG[wp][jj][lane] = G;
                }
                __syncwarp();
            }
        }
    }
    __syncthreads();

    if (t < NP * NUM_J) {
        const float* G = sG[p][j];
        float sh0 = sSh[p][0], sh1 = sSh[p][1], sh2 = sSh[p][2];

        a.outJ[(p*NUM_J + j)*3 + 0] = G[9]  + sh0;
        a.outJ[(p*NUM_J + j)*3 + 1] = G[10] + sh1;
        a.outJ[(p*NUM_J + j)*3 + 2] = G[11] + sh2;

        float jr0 = a.joints[j*3+0], jr1 = a.joints[j*3+1], jr2 = a.joints[j*3+2];
        float tt[3];
        tt[0] = G[9]  - (G[0]*jr0 + G[1]*jr1 + G[2]*jr2) + sh0;
        tt[1] = G[10] - (G[3]*jr0 + G[4]*jr1 + G[5]*jr2) + sh1;
        tt[2] = G[11] - (G[6]*jr0 + G[7]*jr1 + G[8]*jr2) + sh2;

        for (int i = 0; i < 3; i++) {
            int m = 3*p + i;
            float vals[4] = {G[i*3+0], G[i*3+1], G[i*3+2], tt[i]};
            float h[4], l[4];
            for (int c = 0; c < 4; c++) split_bf(vals[c], h[c], l[c]);
            g_Ahi[m*48 + 2*j + 0] = pk2(h[0], h[1]);
            g_Ahi[m*48 + 2*j + 1] = pk2(h[2], h[3]);
            g_Alo[m*48 + 2*j + 0] = pk2(l[0], l[1]);
            g_Alo[m*48 + 2*j + 1] = pk2(l[2], l[3]);
        }
    }
}

// ---------------------------------------------------------------------------
// Kernel 2: 192-vertex tile GEMM via mma.sync (bf16 hi/lo, 3 passes).
// Warp w owns n8 tiles {3w, 3w+1, 3w+2}; each A fragment load feeds 3 MMAs.
// ---------------------------------------------------------------------------
__global__ __launch_bounds__(THREADS, 3) void lbs_mma(const float* __restrict__ verts,
                                                      const float* __restrict__ weights,
                                                      float* __restrict__ out, int V) {
    __shared__ __align__(16) char smem[SMEM_TOTAL];
    uint32_t sb = smem_u32(smem);
    float* sWf = (float*)(smem + OFF_W);
    float* sVf = (float*)(smem + OFF_V);

    int tid  = threadIdx.x;
    int lane = tid & 31;
    int warp = tid >> 5;
    int m4   = lane & 3;
    int grp  = lane >> 2;
    int v0   = blockIdx.x * NT;
    int nv   = min(NT, V - v0);

    // ---- stage A hi/lo ----
    for (int i = tid; i < 48*48; i += THREADS) {
        int m = i / 48, c = i - m*48;
        *(uint32_t*)(smem + OFF_AH + m*SA_STRIDE_B + c*4) = g_Ahi[i];
        *(uint32_t*)(smem + OFF_AL + m*SA_STRIDE_B + c*4) = g_Alo[i];
    }
    // ---- stage weights (zero-fill tail) ----
    {
        const float4* src = (const float4*)(weights + (size_t)v0 * NUM_J);
        int wn4 = (nv * NUM_J) >> 2;          // nv*23 % 4 == 0 for nv in {192,32}
        for (int i = tid; i < (NT*NUM_J)/4; i += THREADS) {
            float4 f = make_float4(0.f, 0.f, 0.f, 0.f);
            if (i < wn4) f = __ldg(src + i);
            *(float4*)(sWf + i*4) = f;
        }
    }
    // ---- stage verts as (x,y,z,1), zeros beyond nv ----
    if (tid < NT) {
        sVf[tid*4 + 3] = 1.0f;
        if (tid >= nv) { sVf[tid*4+0] = 0.f; sVf[tid*4+1] = 0.f; sVf[tid*4+2] = 0.f; }
    }
    {
        int nf4 = (nv * 3) >> 2;
        if (tid < nf4) {
            float4 f = __ldg((const float4*)(verts + (size_t)v0*3) + tid);
            int e = tid * 4;
            sVf[(e/3)*4 + (e%3)] = f.x;
            sVf[((e+1)/3)*4 + ((e+1)%3)] = f.y;
            sVf[((e+2)/3)*4 + ((e+2)%3)] = f.z;
            sVf[((e+3)/3)*4 + ((e+3)%3)] = f.w;
        }
    }
    __syncthreads();

    uint32_t aoff = (uint32_t)((lane & 15) * SA_STRIDE_B + ((lane >> 4) << 4));
    uint32_t aHi = sb + OFF_AH + aoff;
    uint32_t aLo = sb + OFF_AL + aoff;

    // per-tile preload: vertex components + weight row pointers
    float vc0[3], vc1[3];
    const float* wrow[3];
#pragma unroll
    for (int t = 0; t < 3; t++) {
        int vB = (warp*3 + t)*8 + grp;
        float4 vq = *(const float4*)(sVf + vB*4);
        vc0[t] = (m4 & 1) ? vq.z : vq.x;
        vc1[t] = (m4 & 1) ? vq.w : vq.y;
        wrow[t] = sWf + vB * NUM_J;
    }

    float d[3][3][4];
#pragma unroll
    for (int t = 0; t < 3; t++)
#pragma unroll
        for (int mt = 0; mt < 3; mt++)
#pragma unroll
            for (int q = 0; q < 4; q++) d[t][mt][q] = 0.f;

    int jbase = m4 >> 1;

#pragma unroll
    for (int kb = 0; kb < 6; kb++) {
        int jl = 4*kb + jbase;
        int jh = jl + 2;
        uint32_t bh[3][2], bl[3][2];
#pragma unroll
        for (int t = 0; t < 3; t++) {
            float wl = wrow[t][jl];
            float wh = (jh < NUM_J) ? wrow[t][jh] : 0.f;
            float p0 = wl*vc0[t], p1 = wl*vc1[t], p2 = wh*vc0[t], p3 = wh*vc1[t];
            bh[t][0] = cvt2(p0, p1);
            bh[t][1] = cvt2(p2, p3);
            float h0 = __uint_as_float(bh[t][0] << 16);
            float h1 = __uint_as_float(bh[t][0] & 0xffff0000u);
            float h2 = __uint_as_float(bh[t][1] << 16);
            float h3 = __uint_as_float(bh[t][1] & 0xffff0000u);
            bl[t][0] = cvt2(p0 - h0, p1 - h1);
            bl[t][1] = cvt2(p2 - h2, p3 - h3);
        }
#pragma unroll
        for (int mt = 0; mt < 3; mt++) {
            uint32_t a0, a1, a2, a3;
            ldmA(a0, a1, a2, a3, aHi + mt*16*SA_STRIDE_B + kb*32);
            mma16816(d[0][mt], a0, a1, a2, a3, bh[0][0], bh[0][1]);
            mma16816(d[1][mt], a0, a1, a2, a3, bh[1][0], bh[1][1]);
            mma16816(d[2][mt], a0, a1, a2, a3, bh[2][0], bh[2][1]);
            mma16816(d[0][mt], a0, a1, a2, a3, bl[0][0], bl[0][1]);
            mma16816(d[1][mt], a0, a1, a2, a3, bl[1][0], bl[1][1]);
            mma16816(d[2][mt], a0, a1, a2, a3, bl[2][0], bl[2][1]);
            ldmA(a0, a1, a2, a3, aLo + mt*16*SA_STRIDE_B + kb*32);
            mma16816(d[0][mt], a0, a1, a2, a3, bh[0][0], bh[0][1]);
            mma16816(d[1][mt], a0, a1, a2, a3, bh[1][0], bh[1][1]);
            mma16816(d[2][mt], a0, a1, a2, a3, bh[2][0], bh[2][1]);
        }
    }
    __syncthreads();

    // ---- epilogue: D -> smem in output layout [pose][v*3+i] ----
    float* sE = (float*)smem;
#pragma unroll
    for (int t = 0; t < 3; t++) {
        int vb = (warp*3 + t)*8 + 2*m4;
#pragma unroll
        for (int mt = 0; mt < 3; mt++) {
            int r0 = mt*16 + grp;
            int r1 = r0 + 8;
            int pA = r0/3, iA = r0 - 3*pA;
            int pB = r1/3, iB = r1 - 3*pB;
            sE[pA*POSE_STRIDE + vb*3     + iA] = d[t][mt][0];
            sE[pA*POSE_STRIDE + (vb+1)*3 + iA] = d[t][mt][1];
            sE[pB*POSE_STRIDE + vb*3     + iB] = d[t][mt][2];
            sE[pB*POSE_STRIDE + (vb+1)*3 + iB] = d[t][mt][3];
        }
    }
    __syncthreads();

    // ---- coalesced float4 copy out ----
    size_t V3 = (size_t)V * 3;
    int nf4 = (nv * 3) >> 2;                   // valid float4 per pose (144 or 24)
    for (int q = tid; q < NP * 144; q += THREADS) {
        int p = q / 144, r = q - p*144;
        if (r < nf4) {
            float4 val = *(const float4*)(sE + p*POSE_STRIDE + r*4);
            *(float4*)(out + (size_t)p*V3 + (size_t)v0*3 + r*4) = val;
        }
    }
}

// ---------------------------------------------------------------------------
extern "C" void kernel_launch(void* const* d_in, const int* in_sizes, int n_in,
                              void* d_out, int out_size) {
    const float* vertices = (const float*)d_in[0];   // (1,V,3)
    const float* joints   = (const float*)d_in[1];   // (1,23,3)
    const float* weights  = (const float*)d_in[2];   // (V,23)
    const float* disp     = (const float*)d_in[3];   // (16,1,3)
    const float* rnd      = (const float*)d_in[4];   // (16,3)

    int V = in_sizes[0] / 3;
    float* out = (float*)d_out;

    SetupArgs sa;
    sa.joints = joints;
    sa.disp   = disp;
    sa.rnd    = rnd;
    for (int i = 0; i < 11; i++) sa.prm[i] = (const float*)d_in[5 + i];
    sa.outJ = out + (size_t)NP * V * 3;

    lbs_setup<<<1, 512>>>(sa);
    int blocks = (V + NT - 1) / NT;
    lbs_mma<<<blocks, THREADS>>>(vertices, weights, out, V);
}